// round 1
// baseline (speedup 1.0000x reference)
#include <cuda_runtime.h>

#define F_DIM 256
#define H_DIM 256
#define MAXN 50048
#define MAXE 1600512

// ---------------- scratch (static __device__, no allocations) ----------------
__device__ float g_hsum[(size_t)MAXN * F_DIM];   // h = x + agg
__device__ int   g_count[MAXN];
__device__ int   g_start[MAXN];
__device__ int   g_cursor[MAXN];
__device__ int   g_srclist[MAXE];
__device__ int   g_total;
__device__ int   g_is64;
__device__ float g_colsum[H_DIM];
__device__ float g_colsumsq[H_DIM];
__device__ float g_scale[H_DIM];
__device__ float g_shift[H_DIM];

// ---------------- helpers ----------------
__device__ __forceinline__ float4 f4add(float4 a, float4 b) {
    a.x += b.x; a.y += b.y; a.z += b.z; a.w += b.w; return a;
}

// Read edge index entry `pos` handling both int64 and int32 storage.
__device__ __forceinline__ int load_idx(const void* ei, int is64, long long pos) {
    if (is64) return (int)(((const long long*)ei)[pos]);
    return ((const int*)ei)[pos];
}

// ---------------- kernels ----------------

// Detect whether edge_index is int64 (odd 32-bit words all zero) or int32.
__global__ void detect_kernel(const unsigned int* __restrict__ e) {
    __shared__ int nz;
    if (threadIdx.x == 0) nz = 0;
    __syncthreads();
    unsigned int v = e[threadIdx.x * 2 + 1];
    if (v != 0u) atomicAdd(&nz, 1);
    __syncthreads();
    if (threadIdx.x == 0) g_is64 = (nz == 0) ? 1 : 0;
}

__global__ void zero_kernel(int N) {
    int i = blockIdx.x * blockDim.x + threadIdx.x;
    if (i < N) g_count[i] = 0;
    if (i < H_DIM) { g_colsum[i] = 0.0f; g_colsumsq[i] = 0.0f; }
    if (i == 0) g_total = 0;
}

__global__ void hist_kernel(const void* __restrict__ ei, int E) {
    int is64 = g_is64;
    for (int e = blockIdx.x * blockDim.x + threadIdx.x; e < E;
         e += gridDim.x * blockDim.x) {
        int d = load_idx(ei, is64, (long long)E + e);
        atomicAdd(&g_count[d], 1);
    }
}

// Bump-allocate bucket start offsets (order irrelevant -> no scan needed).
__global__ void alloc_kernel(int N) {
    int i = blockIdx.x * blockDim.x + threadIdx.x;
    if (i < N) {
        int c = g_count[i];
        int s = atomicAdd(&g_total, c);
        g_start[i] = s;
        g_cursor[i] = s;
    }
}

__global__ void scatter_kernel(const void* __restrict__ ei, int E) {
    int is64 = g_is64;
    for (int e = blockIdx.x * blockDim.x + threadIdx.x; e < E;
         e += gridDim.x * blockDim.x) {
        int s = load_idx(ei, is64, e);
        int d = load_idx(ei, is64, (long long)E + e);
        int p = atomicAdd(&g_cursor[d], 1);
        g_srclist[p] = s;
    }
}

// Warp-per-node gather: hsum[d] = x[d] + sum_{s in N(d)} x[s]
__global__ void gather_kernel(const float4* __restrict__ x4, int N) {
    int lane = threadIdx.x & 31;
    int warp = (blockIdx.x * blockDim.x + threadIdx.x) >> 5;
    int nwarps = (gridDim.x * blockDim.x) >> 5;
    float4* h4 = (float4*)g_hsum;
    for (int d = warp; d < N; d += nwarps) {
        const float4* xd = x4 + (size_t)d * 64;
        float4 a0 = xd[lane];
        float4 a1 = xd[lane + 32];
        int s = g_start[d];
        int c = g_count[d];
        const int* lst = g_srclist + s;
        int i = 0;
        for (; i + 4 <= c; i += 4) {
            int n0 = lst[i], n1 = lst[i + 1], n2 = lst[i + 2], n3 = lst[i + 3];
            const float4* p0 = x4 + (size_t)n0 * 64;
            const float4* p1 = x4 + (size_t)n1 * 64;
            const float4* p2 = x4 + (size_t)n2 * 64;
            const float4* p3 = x4 + (size_t)n3 * 64;
            float4 v00 = p0[lane], v01 = p0[lane + 32];
            float4 v10 = p1[lane], v11 = p1[lane + 32];
            float4 v20 = p2[lane], v21 = p2[lane + 32];
            float4 v30 = p3[lane], v31 = p3[lane + 32];
            a0 = f4add(a0, v00); a1 = f4add(a1, v01);
            a0 = f4add(a0, v10); a1 = f4add(a1, v11);
            a0 = f4add(a0, v20); a1 = f4add(a1, v21);
            a0 = f4add(a0, v30); a1 = f4add(a1, v31);
        }
        for (; i < c; i++) {
            const float4* p0 = x4 + (size_t)lst[i] * 64;
            a0 = f4add(a0, p0[lane]);
            a1 = f4add(a1, p0[lane + 32]);
        }
        float4* hd = h4 + (size_t)d * 64;
        hd[lane] = a0;
        hd[lane + 32] = a1;
    }
}

// GEMM: out[n][h] = sum_f hsum[n][f] * W[h][f] + b[h]
// Block tile 128 rows x 128 cols, 256 threads, 8x8 micro-tile.
// Epilogue fuses bias + per-column sum / sumsq (BN batch stats).
#define TM 128
#define TC 128
#define KB 32
__global__ void __launch_bounds__(256)
gemm_bn_kernel(const float* __restrict__ bias,
               const float* __restrict__ Wm,
               float* __restrict__ out, int N) {
    __shared__ float As[KB][TM + 4];
    __shared__ float Bs[KB][TC + 4];
    __shared__ float scol[TC];
    __shared__ float scolsq[TC];

    int tid = threadIdx.x;
    int tx = tid & 15;      // col group
    int ty = tid >> 4;      // row group
    int col0 = blockIdx.x * TC;
    int row0 = blockIdx.y * TM;

    float acc[8][8];
#pragma unroll
    for (int i = 0; i < 8; i++)
#pragma unroll
        for (int j = 0; j < 8; j++) acc[i][j] = 0.0f;

    const float4* h4 = (const float4*)g_hsum;
    const float4* w4 = (const float4*)Wm;

    int mloc = tid >> 1;           // 0..127
    int jb = (tid & 1) * 4;        // 0 or 4

    for (int kt = 0; kt < F_DIM / KB; kt++) {
        // load A tile (transpose to [k][m]); guard rows >= N
        int arow = row0 + mloc;
        bool av = (arow < N);
#pragma unroll
        for (int j = 0; j < 4; j++) {
            float4 v = make_float4(0.f, 0.f, 0.f, 0.f);
            if (av) v = h4[(size_t)arow * 64 + kt * 8 + jb + j];
            int k = (jb + j) * 4;
            As[k + 0][mloc] = v.x;
            As[k + 1][mloc] = v.y;
            As[k + 2][mloc] = v.z;
            As[k + 3][mloc] = v.w;
        }
        // load W tile (H=256 so always valid)
#pragma unroll
        for (int j = 0; j < 4; j++) {
            float4 v = w4[(size_t)(col0 + mloc) * 64 + kt * 8 + jb + j];
            int k = (jb + j) * 4;
            Bs[k + 0][mloc] = v.x;
            Bs[k + 1][mloc] = v.y;
            Bs[k + 2][mloc] = v.z;
            Bs[k + 3][mloc] = v.w;
        }
        __syncthreads();
#pragma unroll
        for (int kk = 0; kk < KB; kk++) {
            float a[8], bb[8];
            *(float4*)&a[0] = *(const float4*)&As[kk][ty * 8];
            *(float4*)&a[4] = *(const float4*)&As[kk][ty * 8 + 4];
            *(float4*)&bb[0] = *(const float4*)&Bs[kk][tx * 8];
            *(float4*)&bb[4] = *(const float4*)&Bs[kk][tx * 8 + 4];
#pragma unroll
            for (int i = 0; i < 8; i++)
#pragma unroll
                for (int j = 0; j < 8; j++) acc[i][j] += a[i] * bb[j];
        }
        __syncthreads();
    }

    // epilogue
    if (tid < TC) { scol[tid] = 0.0f; scolsq[tid] = 0.0f; }
    __syncthreads();

    float bv[8];
#pragma unroll
    for (int j = 0; j < 8; j++) bv[j] = bias[col0 + tx * 8 + j];

#pragma unroll
    for (int i = 0; i < 8; i++) {
        int row = row0 + ty * 8 + i;
        if (row < N) {
            float vals[8];
#pragma unroll
            for (int j = 0; j < 8; j++) vals[j] = acc[i][j] + bv[j];
            float4* op = (float4*)(out + (size_t)row * H_DIM + col0 + tx * 8);
            op[0] = make_float4(vals[0], vals[1], vals[2], vals[3]);
            op[1] = make_float4(vals[4], vals[5], vals[6], vals[7]);
        }
    }

    // per-column partial stats -> smem atomics -> one global atomic per column
#pragma unroll
    for (int j = 0; j < 8; j++) {
        float s = 0.0f, q = 0.0f;
#pragma unroll
        for (int i = 0; i < 8; i++) {
            int row = row0 + ty * 8 + i;
            if (row < N) {
                float v = acc[i][j] + bv[j];
                s += v;
                q += v * v;
            }
        }
        atomicAdd(&scol[tx * 8 + j], s);
        atomicAdd(&scolsq[tx * 8 + j], q);
    }
    __syncthreads();
    if (tid < TC) {
        atomicAdd(&g_colsum[col0 + tid], scol[tid]);
        atomicAdd(&g_colsumsq[col0 + tid], scolsq[tid]);
    }
}

__global__ void bn_finalize_kernel(const float* __restrict__ bn_w,
                                   const float* __restrict__ bn_b, int N) {
    int c = threadIdx.x;
    if (c < H_DIM) {
        float inv = 1.0f / (float)N;
        float mean = g_colsum[c] * inv;
        float var = g_colsumsq[c] * inv - mean * mean;
        float sc = bn_w[c] * rsqrtf(var + 1e-5f);
        g_scale[c] = sc;
        g_shift[c] = bn_b[c] - mean * sc;
    }
}

__global__ void normalize_kernel(float4* __restrict__ out, int n4) {
    const float4* sc4 = (const float4*)g_scale;
    const float4* sh4 = (const float4*)g_shift;
    for (int i = blockIdx.x * blockDim.x + threadIdx.x; i < n4;
         i += gridDim.x * blockDim.x) {
        float4 v = out[i];
        int c = i & 63;  // 64 float4 per row of 256
        float4 sc = sc4[c];
        float4 sh = sh4[c];
        v.x = v.x * sc.x + sh.x;
        v.y = v.y * sc.y + sh.y;
        v.z = v.z * sc.z + sh.z;
        v.w = v.w * sc.w + sh.w;
        out[i] = v;
    }
}

// ---------------- launch ----------------
extern "C" void kernel_launch(void* const* d_in, const int* in_sizes, int n_in,
                              void* d_out, int out_size) {
    const float* x = (const float*)d_in[0];
    const void* ei = d_in[1];
    const float* W = (const float*)d_in[2];
    const float* b = (const float*)d_in[3];
    const float* bn_w = (const float*)d_in[4];
    const float* bn_b = (const float*)d_in[5];
    float* out = (float*)d_out;

    int N = in_sizes[0] / F_DIM;
    int E = in_sizes[1] / 2;

    detect_kernel<<<1, 256>>>((const unsigned int*)ei);
    zero_kernel<<<(N + 255) / 256, 256>>>(N);
    hist_kernel<<<2048, 256>>>(ei, E);
    alloc_kernel<<<(N + 255) / 256, 256>>>(N);
    scatter_kernel<<<2048, 256>>>(ei, E);
    gather_kernel<<<6272, 256>>>((const float4*)x, N);

    dim3 gg(H_DIM / TC, (N + TM - 1) / TM);
    gemm_bn_kernel<<<gg, 256>>>(b, W, out, N);
    bn_finalize_kernel<<<1, 256>>>(bn_w, bn_b, N);
    normalize_kernel<<<2048, 256>>>((float4*)out, N * (F_DIM / 4));
}

// round 2
// speedup vs baseline: 1.0013x; 1.0013x over previous
#include <cuda_runtime.h>

#define F_DIM 256
#define H_DIM 256
#define MAXN 50048
#define MAXE 1600512

// ---------------- scratch (static __device__, no allocations) ----------------
__device__ float g_hsum[(size_t)MAXN * F_DIM];   // h = x + agg
__device__ int   g_count[MAXN];
__device__ int   g_start[MAXN];
__device__ int   g_cursor[MAXN];
__device__ int   g_srclist[MAXE];
__device__ int   g_total;
__device__ int   g_is64;
__device__ float g_colsum[H_DIM];
__device__ float g_colsumsq[H_DIM];
__device__ float g_scale[H_DIM];
__device__ float g_shift[H_DIM];

// ---------------- helpers ----------------
__device__ __forceinline__ float4 f4add(float4 a, float4 b) {
    a.x += b.x; a.y += b.y; a.z += b.z; a.w += b.w; return a;
}

__device__ __forceinline__ int load_idx(const void* ei, int is64, long long pos) {
    if (is64) return (int)(((const long long*)ei)[pos]);
    return ((const int*)ei)[pos];
}

// packed f32x2 fma: d = a*b + d  (both halves)
__device__ __forceinline__ void fma2(unsigned long long& d,
                                     unsigned long long a,
                                     unsigned long long b) {
    asm("fma.rn.f32x2 %0, %1, %2, %0;" : "+l"(d) : "l"(a), "l"(b));
}
__device__ __forceinline__ unsigned long long pack_dup(float v) {
    unsigned long long r;
    asm("mov.b64 %0, {%1, %1};" : "=l"(r) : "f"(v));
    return r;
}
__device__ __forceinline__ void unpack2(unsigned long long v, float& lo, float& hi) {
    asm("mov.b64 {%0, %1}, %2;" : "=f"(lo), "=f"(hi) : "l"(v));
}

// ---------------- kernels ----------------

__global__ void detect_kernel(const unsigned int* __restrict__ e) {
    __shared__ int nz;
    if (threadIdx.x == 0) nz = 0;
    __syncthreads();
    unsigned int v = e[threadIdx.x * 2 + 1];
    if (v != 0u) atomicAdd(&nz, 1);
    __syncthreads();
    if (threadIdx.x == 0) g_is64 = (nz == 0) ? 1 : 0;
}

__global__ void zero_kernel(int N) {
    int i = blockIdx.x * blockDim.x + threadIdx.x;
    if (i < N) g_count[i] = 0;
    if (i < H_DIM) { g_colsum[i] = 0.0f; g_colsumsq[i] = 0.0f; }
    if (i == 0) g_total = 0;
}

__global__ void hist_kernel(const void* __restrict__ ei, int E) {
    int is64 = g_is64;
    for (int e = blockIdx.x * blockDim.x + threadIdx.x; e < E;
         e += gridDim.x * blockDim.x) {
        int d = load_idx(ei, is64, (long long)E + e);
        atomicAdd(&g_count[d], 1);
    }
}

__global__ void alloc_kernel(int N) {
    int i = blockIdx.x * blockDim.x + threadIdx.x;
    if (i < N) {
        int c = g_count[i];
        int s = atomicAdd(&g_total, c);
        g_start[i] = s;
        g_cursor[i] = s;
    }
}

__global__ void scatter_kernel(const void* __restrict__ ei, int E) {
    int is64 = g_is64;
    for (int e = blockIdx.x * blockDim.x + threadIdx.x; e < E;
         e += gridDim.x * blockDim.x) {
        int s = load_idx(ei, is64, e);
        int d = load_idx(ei, is64, (long long)E + e);
        int p = atomicAdd(&g_cursor[d], 1);
        g_srclist[p] = s;
    }
}

// Warp-per-node gather: hsum[d] = x[d] + sum_{s in N(d)} x[s]
__global__ void gather_kernel(const float4* __restrict__ x4, int N) {
    int lane = threadIdx.x & 31;
    int warp = (blockIdx.x * blockDim.x + threadIdx.x) >> 5;
    int nwarps = (gridDim.x * blockDim.x) >> 5;
    float4* h4 = (float4*)g_hsum;
    for (int d = warp; d < N; d += nwarps) {
        const float4* xd = x4 + (size_t)d * 64;
        float4 a0 = xd[lane];
        float4 a1 = xd[lane + 32];
        int s = g_start[d];
        int c = g_count[d];
        const int* lst = g_srclist + s;
        int i = 0;
        for (; i + 4 <= c; i += 4) {
            int n0 = lst[i], n1 = lst[i + 1], n2 = lst[i + 2], n3 = lst[i + 3];
            const float4* p0 = x4 + (size_t)n0 * 64;
            const float4* p1 = x4 + (size_t)n1 * 64;
            const float4* p2 = x4 + (size_t)n2 * 64;
            const float4* p3 = x4 + (size_t)n3 * 64;
            float4 v00 = p0[lane], v01 = p0[lane + 32];
            float4 v10 = p1[lane], v11 = p1[lane + 32];
            float4 v20 = p2[lane], v21 = p2[lane + 32];
            float4 v30 = p3[lane], v31 = p3[lane + 32];
            a0 = f4add(a0, v00); a1 = f4add(a1, v01);
            a0 = f4add(a0, v10); a1 = f4add(a1, v11);
            a0 = f4add(a0, v20); a1 = f4add(a1, v21);
            a0 = f4add(a0, v30); a1 = f4add(a1, v31);
        }
        for (; i < c; i++) {
            const float4* p0 = x4 + (size_t)lst[i] * 64;
            a0 = f4add(a0, p0[lane]);
            a1 = f4add(a1, p0[lane + 32]);
        }
        float4* hd = h4 + (size_t)d * 64;
        hd[lane] = a0;
        hd[lane + 32] = a1;
    }
}

// GEMM: out[n][h] = sum_f hsum[n][f] * W[h][f] + b[h]
// 128x128 block tile, 256 threads, 8x8 micro-tile with packed f32x2 FMA.
#define TM 128
#define TC 128
#define KB 32
__global__ void __launch_bounds__(256)
gemm_bn_kernel(const float* __restrict__ bias,
               const float* __restrict__ Wm,
               float* __restrict__ out, int N) {
    __shared__ float As[KB][TM + 4];
    __shared__ float Bs[KB][TC + 4];
    __shared__ float scol[TC];
    __shared__ float scolsq[TC];

    int tid = threadIdx.x;
    int tx = tid & 15;      // col group (8 cols)
    int ty = tid >> 4;      // row group (8 rows)
    int col0 = blockIdx.x * TC;
    int row0 = blockIdx.y * TM;

    // packed accumulators: acc2[i][j2] holds cols (2*j2, 2*j2+1) for row i
    unsigned long long acc2[8][4];
#pragma unroll
    for (int i = 0; i < 8; i++)
#pragma unroll
        for (int j = 0; j < 4; j++) acc2[i][j] = 0ULL;

    const float4* h4 = (const float4*)g_hsum;
    const float4* w4 = (const float4*)Wm;

    int mloc = tid >> 1;           // 0..127
    int jb = (tid & 1) * 4;        // 0 or 4

    for (int kt = 0; kt < F_DIM / KB; kt++) {
        int arow = row0 + mloc;
        bool av = (arow < N);
#pragma unroll
        for (int j = 0; j < 4; j++) {
            float4 v = make_float4(0.f, 0.f, 0.f, 0.f);
            if (av) v = h4[(size_t)arow * 64 + kt * 8 + jb + j];
            int k = (jb + j) * 4;
            As[k + 0][mloc] = v.x;
            As[k + 1][mloc] = v.y;
            As[k + 2][mloc] = v.z;
            As[k + 3][mloc] = v.w;
        }
#pragma unroll
        for (int j = 0; j < 4; j++) {
            float4 v = w4[(size_t)(col0 + mloc) * 64 + kt * 8 + jb + j];
            int k = (jb + j) * 4;
            Bs[k + 0][mloc] = v.x;
            Bs[k + 1][mloc] = v.y;
            Bs[k + 2][mloc] = v.z;
            Bs[k + 3][mloc] = v.w;
        }
        __syncthreads();
#pragma unroll
        for (int kk = 0; kk < KB; kk++) {
            float a[8];
            *(float4*)&a[0] = *(const float4*)&As[kk][ty * 8];
            *(float4*)&a[4] = *(const float4*)&As[kk][ty * 8 + 4];
            // B as packed 64-bit column pairs (32B-aligned smem)
            ulonglong2 b01 = *(const ulonglong2*)&Bs[kk][tx * 8];
            ulonglong2 b23 = *(const ulonglong2*)&Bs[kk][tx * 8 + 4];
            unsigned long long bb2[4] = {b01.x, b01.y, b23.x, b23.y};
#pragma unroll
            for (int i = 0; i < 8; i++) {
                unsigned long long a2 = pack_dup(a[i]);
#pragma unroll
                for (int j = 0; j < 4; j++) fma2(acc2[i][j], a2, bb2[j]);
            }
        }
        __syncthreads();
    }

    // epilogue: unpack, bias, store, per-column BN stats
    if (tid < TC) { scol[tid] = 0.0f; scolsq[tid] = 0.0f; }
    __syncthreads();

    float bv[8];
#pragma unroll
    for (int j = 0; j < 8; j++) bv[j] = bias[col0 + tx * 8 + j];

    float accf[8][8];
#pragma unroll
    for (int i = 0; i < 8; i++)
#pragma unroll
        for (int j = 0; j < 4; j++)
            unpack2(acc2[i][j], accf[i][2 * j], accf[i][2 * j + 1]);

#pragma unroll
    for (int i = 0; i < 8; i++) {
        int row = row0 + ty * 8 + i;
        if (row < N) {
            float vals[8];
#pragma unroll
            for (int j = 0; j < 8; j++) vals[j] = accf[i][j] + bv[j];
            float4* op = (float4*)(out + (size_t)row * H_DIM + col0 + tx * 8);
            op[0] = make_float4(vals[0], vals[1], vals[2], vals[3]);
            op[1] = make_float4(vals[4], vals[5], vals[6], vals[7]);
        }
    }

#pragma unroll
    for (int j = 0; j < 8; j++) {
        float s = 0.0f, q = 0.0f;
#pragma unroll
        for (int i = 0; i < 8; i++) {
            int row = row0 + ty * 8 + i;
            if (row < N) {
                float v = accf[i][j] + bv[j];
                s += v;
                q += v * v;
            }
        }
        atomicAdd(&scol[tx * 8 + j], s);
        atomicAdd(&scolsq[tx * 8 + j], q);
    }
    __syncthreads();
    if (tid < TC) {
        atomicAdd(&g_colsum[col0 + tid], scol[tid]);
        atomicAdd(&g_colsumsq[col0 + tid], scolsq[tid]);
    }
}

__global__ void bn_finalize_kernel(const float* __restrict__ bn_w,
                                   const float* __restrict__ bn_b, int N) {
    int c = threadIdx.x;
    if (c < H_DIM) {
        float inv = 1.0f / (float)N;
        float mean = g_colsum[c] * inv;
        float var = g_colsumsq[c] * inv - mean * mean;
        float sc = bn_w[c] * rsqrtf(var + 1e-5f);
        g_scale[c] = sc;
        g_shift[c] = bn_b[c] - mean * sc;
    }
}

__global__ void normalize_kernel(float4* __restrict__ out, int n4) {
    const float4* sc4 = (const float4*)g_scale;
    const float4* sh4 = (const float4*)g_shift;
    for (int i = blockIdx.x * blockDim.x + threadIdx.x; i < n4;
         i += gridDim.x * blockDim.x) {
        float4 v = out[i];
        int c = i & 63;
        float4 sc = sc4[c];
        float4 sh = sh4[c];
        v.x = v.x * sc.x + sh.x;
        v.y = v.y * sc.y + sh.y;
        v.z = v.z * sc.z + sh.z;
        v.w = v.w * sc.w + sh.w;
        out[i] = v;
    }
}

// ---------------- launch ----------------
extern "C" void kernel_launch(void* const* d_in, const int* in_sizes, int n_in,
                              void* d_out, int out_size) {
    const float* x = (const float*)d_in[0];
    const void* ei = d_in[1];
    const float* W = (const float*)d_in[2];
    const float* b = (const float*)d_in[3];
    const float* bn_w = (const float*)d_in[4];
    const float* bn_b = (const float*)d_in[5];
    float* out = (float*)d_out;

    int N = in_sizes[0] / F_DIM;
    int E = in_sizes[1] / 2;

    detect_kernel<<<1, 256>>>((const unsigned int*)ei);
    zero_kernel<<<(N + 255) / 256, 256>>>(N);
    hist_kernel<<<2048, 256>>>(ei, E);
    alloc_kernel<<<(N + 255) / 256, 256>>>(N);
    scatter_kernel<<<2048, 256>>>(ei, E);
    gather_kernel<<<6272, 256>>>((const float4*)x, N);

    dim3 gg(H_DIM / TC, (N + TM - 1) / TM);
    gemm_bn_kernel<<<gg, 256>>>(b, W, out, N);
    bn_finalize_kernel<<<1, 256>>>(bn_w, bn_b, N);
    normalize_kernel<<<2048, 256>>>((float4*)out, N * (F_DIM / 4));
}

// round 6
// speedup vs baseline: 1.4765x; 1.4745x over previous
#include <cuda_runtime.h>
#include <cstdint>

#define F_DIM 256
#define H_DIM 256
#define MAXN 50048
#define MAXE 1600512

// ---------------- scratch ----------------
__device__ float g_hsum[(size_t)MAXN * F_DIM];   // h = x + agg (tf32-rounded)
__device__ float g_wtf32[H_DIM * F_DIM];         // W rounded to tf32
__device__ int   g_count[MAXN];
__device__ int   g_start[MAXN];
__device__ int   g_cursor[MAXN];
__device__ int   g_srclist[MAXE];
__device__ int   g_total;
__device__ int   g_is64;
__device__ float g_colsum[H_DIM];
__device__ float g_colsumsq[H_DIM];
__device__ float g_scale[H_DIM];
__device__ float g_shift[H_DIM];

// ---------------- helpers ----------------
__device__ __forceinline__ float4 f4add(float4 a, float4 b) {
    a.x += b.x; a.y += b.y; a.z += b.z; a.w += b.w; return a;
}
__device__ __forceinline__ int load_idx(const void* ei, int is64, long long pos) {
    if (is64) return (int)(((const long long*)ei)[pos]);
    return ((const int*)ei)[pos];
}
__device__ __forceinline__ float tf32_rna(float x) {
    float r;
    asm("cvt.rna.tf32.f32 %0, %1;" : "=f"(r) : "f"(x));
    return r;
}

// mma.sync m16n8k8 tf32: D += A*B, in-place accumulate
__device__ __forceinline__ void mma1688(float4& d, const float4 a, const float2 b) {
    asm volatile(
        "mma.sync.aligned.m16n8k8.row.col.f32.tf32.tf32.f32 "
        "{%0,%1,%2,%3}, {%4,%5,%6,%7}, {%8,%9}, {%0,%1,%2,%3};"
        : "+f"(d.x), "+f"(d.y), "+f"(d.z), "+f"(d.w)
        : "r"(__float_as_uint(a.x)), "r"(__float_as_uint(a.y)),
          "r"(__float_as_uint(a.z)), "r"(__float_as_uint(a.w)),
          "r"(__float_as_uint(b.x)), "r"(__float_as_uint(b.y)));
}

// ---------------- prep kernels ----------------
__global__ void detect_kernel(const unsigned int* __restrict__ e) {
    __shared__ int nz;
    if (threadIdx.x == 0) nz = 0;
    __syncthreads();
    unsigned int v = e[threadIdx.x * 2 + 1];
    if (v != 0u) atomicAdd(&nz, 1);
    __syncthreads();
    if (threadIdx.x == 0) g_is64 = (nz == 0) ? 1 : 0;
}

__global__ void zero_kernel(int N) {
    int i = blockIdx.x * blockDim.x + threadIdx.x;
    if (i < N) g_count[i] = 0;
    if (i < H_DIM) { g_colsum[i] = 0.0f; g_colsumsq[i] = 0.0f; }
    if (i == 0) g_total = 0;
}

__global__ void wconv_kernel(const float* __restrict__ W) {
    int i = blockIdx.x * blockDim.x + threadIdx.x;
    g_wtf32[i] = tf32_rna(W[i]);
}

__global__ void hist_kernel(const void* __restrict__ ei, int E) {
    int is64 = g_is64;
    for (int e = blockIdx.x * blockDim.x + threadIdx.x; e < E;
         e += gridDim.x * blockDim.x) {
        int d = load_idx(ei, is64, (long long)E + e);
        atomicAdd(&g_count[d], 1);
    }
}

__global__ void alloc_kernel(int N) {
    int i = blockIdx.x * blockDim.x + threadIdx.x;
    if (i < N) {
        int c = g_count[i];
        int s = atomicAdd(&g_total, c);
        g_start[i] = s;
        g_cursor[i] = s;
    }
}

__global__ void scatter_kernel(const void* __restrict__ ei, int E) {
    int is64 = g_is64;
    for (int e = blockIdx.x * blockDim.x + threadIdx.x; e < E;
         e += gridDim.x * blockDim.x) {
        int s = load_idx(ei, is64, e);
        int d = load_idx(ei, is64, (long long)E + e);
        int p = atomicAdd(&g_cursor[d], 1);
        g_srclist[p] = s;
    }
}

// Warp-per-node gather: hsum[d] = tf32_round(x[d] + sum_{s in N(d)} x[s])
__global__ void gather_kernel(const float4* __restrict__ x4, int N) {
    int lane = threadIdx.x & 31;
    int warp = (blockIdx.x * blockDim.x + threadIdx.x) >> 5;
    int nwarps = (gridDim.x * blockDim.x) >> 5;
    float4* h4 = (float4*)g_hsum;
    for (int d = warp; d < N; d += nwarps) {
        const float4* xd = x4 + (size_t)d * 64;
        float4 a0 = xd[lane];
        float4 a1 = xd[lane + 32];
        int s = g_start[d];
        int c = g_count[d];
        const int* lst = g_srclist + s;
        int i = 0;
        for (; i + 4 <= c; i += 4) {
            int n0 = lst[i], n1 = lst[i + 1], n2 = lst[i + 2], n3 = lst[i + 3];
            const float4* p0 = x4 + (size_t)n0 * 64;
            const float4* p1 = x4 + (size_t)n1 * 64;
            const float4* p2 = x4 + (size_t)n2 * 64;
            const float4* p3 = x4 + (size_t)n3 * 64;
            float4 v00 = p0[lane], v01 = p0[lane + 32];
            float4 v10 = p1[lane], v11 = p1[lane + 32];
            float4 v20 = p2[lane], v21 = p2[lane + 32];
            float4 v30 = p3[lane], v31 = p3[lane + 32];
            a0 = f4add(a0, v00); a1 = f4add(a1, v01);
            a0 = f4add(a0, v10); a1 = f4add(a1, v11);
            a0 = f4add(a0, v20); a1 = f4add(a1, v21);
            a0 = f4add(a0, v30); a1 = f4add(a1, v31);
        }
        for (; i < c; i++) {
            const float4* p0 = x4 + (size_t)lst[i] * 64;
            a0 = f4add(a0, p0[lane]);
            a1 = f4add(a1, p0[lane + 32]);
        }
        a0.x = tf32_rna(a0.x); a0.y = tf32_rna(a0.y);
        a0.z = tf32_rna(a0.z); a0.w = tf32_rna(a0.w);
        a1.x = tf32_rna(a1.x); a1.y = tf32_rna(a1.y);
        a1.z = tf32_rna(a1.z); a1.w = tf32_rna(a1.w);
        float4* hd = h4 + (size_t)d * 64;
        hd[lane] = a0;
        hd[lane + 32] = a1;
    }
}

// ---------------- mma.sync tf32 GEMM ----------------
// out[n][h] = sum_f hsum[n][f] * W[h][f] + b[h], fused BN stats.
// CTA tile M=128 x N=256, K chunks of 32, 8 warps (2m x 4n), warp tile 64x64.
// Smem in fragment-permuted layout:
//   A: tile(mt 0..7, kt 0..3) base (mt*4+kt)*512B, lane*16B holds {a0,a1,a2,a3}
//   B: tile(nt 0..31, kt 0..3) base (nt*4+kt)*256B, lane*8B holds {b0,b1}
#define A_BYTES 16384
#define B_BYTES 32768
#define STAGE_BYTES (A_BYTES + B_BYTES)
#define SM_TOTAL (2 * STAGE_BYTES)

__device__ __forceinline__ void ldg_chunk(int row0, int ck,
                                          float4 (&ar)[4], float4 (&br)[8]) {
    int tid = threadIdx.x;
#pragma unroll
    for (int i = 0; i < 4; i++) {
        int idx = tid + i * 256;         // 1024 float4: row = idx>>3, f = idx&7
        ar[i] = *(const float4*)(g_hsum + (size_t)(row0 + (idx >> 3)) * 256 +
                                 ck * 32 + (idx & 7) * 4);
    }
#pragma unroll
    for (int i = 0; i < 8; i++) {
        int idx = tid + i * 256;         // 2048 float4: n = idx>>3, f = idx&7
        br[i] = *(const float4*)(g_wtf32 + (size_t)(idx >> 3) * 256 +
                                 ck * 32 + (idx & 7) * 4);
    }
}

__device__ __forceinline__ void sts_chunk(char* sm, uint32_t abase, uint32_t bbase,
                                          const float4 (&ar)[4], const float4 (&br)[8]) {
    int tid = threadIdx.x;
#pragma unroll
    for (int i = 0; i < 4; i++) {
        int idx = tid + i * 256;
        int row = idx >> 3, f = idx & 7;
        int mt = row >> 4, rr = row & 15;
        int kt = f >> 1;
        int reg = (rr >> 3) + 2 * (f & 1);
        uint32_t base = abase + (uint32_t)((mt * 4 + kt) * 512 + reg * 4 +
                                           (rr & 7) * 4 * 16);
        const float* v = (const float*)&ar[i];
#pragma unroll
        for (int j = 0; j < 4; j++)
            *(float*)(sm + base + j * 16) = v[j];
    }
#pragma unroll
    for (int i = 0; i < 8; i++) {
        int idx = tid + i * 256;
        int n = idx >> 3, f = idx & 7;
        int nt = n >> 3, nn = n & 7;
        int kt = f >> 1;
        int reg = f & 1;
        uint32_t base = bbase + (uint32_t)((nt * 4 + kt) * 256 + reg * 4 + nn * 4 * 8);
        const float* v = (const float*)&br[i];
#pragma unroll
        for (int j = 0; j < 4; j++)
            *(float*)(sm + base + j * 8) = v[j];
    }
}

__global__ void __launch_bounds__(256, 1)
gemm_mma_kernel(const float* __restrict__ bias, float* __restrict__ out, int N) {
    extern __shared__ char sm[];
    int tid = threadIdx.x;
    int lane = tid & 31;
    int wid = tid >> 5;
    int wm = wid >> 2;          // 0..1
    int wn = wid & 3;           // 0..3
    int row0 = blockIdx.x * 128;

    float4 acc[4][8];
#pragma unroll
    for (int m = 0; m < 4; m++)
#pragma unroll
        for (int n = 0; n < 8; n++) acc[m][n] = make_float4(0.f, 0.f, 0.f, 0.f);

    float4 ar[4];
    float4 br[8];

    // prologue: chunk 0 -> stage 0
    ldg_chunk(row0, 0, ar, br);
    sts_chunk(sm, 0, A_BYTES, ar, br);
    __syncthreads();

#pragma unroll 1
    for (int c = 0; c < 8; c++) {
        if (c < 7) ldg_chunk(row0, c + 1, ar, br);

        uint32_t ab = (c & 1) ? (uint32_t)STAGE_BYTES : 0u;
        uint32_t bb = ab + A_BYTES;
#pragma unroll
        for (int kt = 0; kt < 4; kt++) {
            float4 af[4];
            float2 bf[8];
#pragma unroll
            for (int m = 0; m < 4; m++)
                af[m] = *(const float4*)(sm + ab +
                                         ((wm * 4 + m) * 4 + kt) * 512 + lane * 16);
#pragma unroll
            for (int n = 0; n < 8; n++)
                bf[n] = *(const float2*)(sm + bb +
                                         ((wn * 8 + n) * 4 + kt) * 256 + lane * 8);
#pragma unroll
            for (int m = 0; m < 4; m++)
#pragma unroll
                for (int n = 0; n < 8; n++) mma1688(acc[m][n], af[m], bf[n]);
        }

        if (c < 7) {
            uint32_t nab = ((c + 1) & 1) ? (uint32_t)STAGE_BYTES : 0u;
            sts_chunk(sm, nab, nab + A_BYTES, ar, br);
        }
        __syncthreads();
    }

    // ---------------- epilogue: bias + store + BN stats ----------------
    float2 bv[8];
#pragma unroll
    for (int n = 0; n < 8; n++)
        bv[n] = *(const float2*)(bias + wn * 64 + n * 8 + 2 * (lane & 3));

    float s0[8], s1[8], q0[8], q1[8];
#pragma unroll
    for (int n = 0; n < 8; n++) { s0[n] = s1[n] = q0[n] = q1[n] = 0.f; }

#pragma unroll
    for (int m = 0; m < 4; m++) {
        int r0g = row0 + wm * 64 + m * 16 + (lane >> 2);
        bool v0 = (r0g < N);
        bool v8 = (r0g + 8 < N);
#pragma unroll
        for (int n = 0; n < 8; n++) {
            int col = wn * 64 + n * 8 + 2 * (lane & 3);
            float x0 = acc[m][n].x + bv[n].x;
            float x1 = acc[m][n].y + bv[n].y;
            float x2 = acc[m][n].z + bv[n].x;
            float x3 = acc[m][n].w + bv[n].y;
            if (v0) {
                *(float2*)(out + (size_t)r0g * H_DIM + col) = make_float2(x0, x1);
                s0[n] += x0; s1[n] += x1;
                q0[n] += x0 * x0; q1[n] += x1 * x1;
            }
            if (v8) {
                *(float2*)(out + (size_t)(r0g + 8) * H_DIM + col) = make_float2(x2, x3);
                s0[n] += x2; s1[n] += x3;
                q0[n] += x2 * x2; q1[n] += x3 * x3;
            }
        }
    }

    // reduce over lanes with same (lane&3): strides 16, 8, 4
#pragma unroll
    for (int n = 0; n < 8; n++) {
#pragma unroll
        for (int off = 16; off >= 4; off >>= 1) {
            s0[n] += __shfl_down_sync(0xffffffffu, s0[n], off);
            s1[n] += __shfl_down_sync(0xffffffffu, s1[n], off);
            q0[n] += __shfl_down_sync(0xffffffffu, q0[n], off);
            q1[n] += __shfl_down_sync(0xffffffffu, q1[n], off);
        }
        if (lane < 4) {
            int col = wn * 64 + n * 8 + 2 * lane;
            atomicAdd(&g_colsum[col], s0[n]);
            atomicAdd(&g_colsum[col + 1], s1[n]);
            atomicAdd(&g_colsumsq[col], q0[n]);
            atomicAdd(&g_colsumsq[col + 1], q1[n]);
        }
    }
}

// ---------------- BN finalize / normalize ----------------
__global__ void bn_finalize_kernel(const float* __restrict__ bn_w,
                                   const float* __restrict__ bn_b, int N) {
    int c = threadIdx.x;
    if (c < H_DIM) {
        float inv = 1.0f / (float)N;
        float mean = g_colsum[c] * inv;
        float var = g_colsumsq[c] * inv - mean * mean;
        float sc = bn_w[c] * rsqrtf(var + 1e-5f);
        g_scale[c] = sc;
        g_shift[c] = bn_b[c] - mean * sc;
    }
}

__global__ void normalize_kernel(float4* __restrict__ out, int n4) {
    const float4* sc4 = (const float4*)g_scale;
    const float4* sh4 = (const float4*)g_shift;
    for (int i = blockIdx.x * blockDim.x + threadIdx.x; i < n4;
         i += gridDim.x * blockDim.x) {
        float4 v = out[i];
        int c = i & 63;
        float4 sc = sc4[c];
        float4 sh = sh4[c];
        v.x = v.x * sc.x + sh.x;
        v.y = v.y * sc.y + sh.y;
        v.z = v.z * sc.z + sh.z;
        v.w = v.w * sc.w + sh.w;
        out[i] = v;
    }
}

// ---------------- launch ----------------
extern "C" void kernel_launch(void* const* d_in, const int* in_sizes, int n_in,
                              void* d_out, int out_size) {
    const float* x = (const float*)d_in[0];
    const void* ei = d_in[1];
    const float* W = (const float*)d_in[2];
    const float* b = (const float*)d_in[3];
    const float* bn_w = (const float*)d_in[4];
    const float* bn_b = (const float*)d_in[5];
    float* out = (float*)d_out;

    int N = in_sizes[0] / F_DIM;
    int E = in_sizes[1] / 2;
    int grid_m = (N + 127) / 128;

    cudaFuncSetAttribute(gemm_mma_kernel,
                         cudaFuncAttributeMaxDynamicSharedMemorySize, SM_TOTAL);

    detect_kernel<<<1, 256>>>((const unsigned int*)ei);
    zero_kernel<<<(N + 255) / 256, 256>>>(N);
    wconv_kernel<<<(H_DIM * F_DIM) / 256, 256>>>(W);
    hist_kernel<<<2048, 256>>>(ei, E);
    alloc_kernel<<<(N + 255) / 256, 256>>>(N);
    scatter_kernel<<<2048, 256>>>(ei, E);
    gather_kernel<<<6272, 256>>>((const float4*)x, N);

    gemm_mma_kernel<<<grid_m, 256, SM_TOTAL>>>(b, out, N);
    bn_finalize_kernel<<<1, 256>>>(bn_w, bn_b, N);
    normalize_kernel<<<2048, 256>>>((float4*)out, N * (F_DIM / 4));
}